// round 15
// baseline (speedup 1.0000x reference)
#include <cuda_runtime.h>

#define NN 6144
#define EE 196608
#define NB 148
#define NT 1024
#define NTH (NB*NT)       // 151552
#define DMAX 96
#define L2E 1.4426950408889634f

__device__ unsigned g_gen;        // zero at load; monotonic across launches
__device__ unsigned g_count;      // self-resetting

// All state below is zero at module load and restored to zero by the end of
// every launch (zero-on-last-use), so replays see identical initial state.
static __device__ int    g_deg[NN];
static __device__ int    g_csr[NN*DMAX];
static __device__ float4 g_xp[2][NN];     // xyz = xp, w = asrc*L2E
static __device__ float  g_dvv[2][NN];    // adst*L2E
static __device__ float4 g_q[NN];         // mha q * L2E
static __device__ float4 g_kv[2*NN];      // [2i]=k, [2i+1]=v
static __device__ float  g_acc[NN*8];     // z0..z2,o0..o2 (atomic); re-zeroed in P13
static __device__ float4 g_tcq[NN];       // q2 * (1/sqrt3)*L2E
static __device__ float4 g_tckv[2*NN];    // [2i]=k2, [2i+1]=v2
static __device__ float4 g_skip[NN];
static __device__ float  g_flat[3*NN];
static __device__ float  g_h1[16];        // atomic accum; reset by last block
static __device__ float  g_sum;           // reset by last block
static __device__ unsigned g_flag;        // reset by last block

__device__ __forceinline__ float ex2f(float x){ float y; asm("ex2.approx.ftz.f32 %0,%1;":"=f"(y):"f"(x)); return y; }
__device__ __forceinline__ unsigned ld_acq(unsigned* p){
  unsigned v; asm volatile("ld.acquire.gpu.global.u32 %0,[%1];":"=r"(v):"l"(p):"memory"); return v;
}

// Flat grid barrier — 148 co-resident blocks (1 block/SM: 1024thr x 64regs
// fills the RF). Only 148 arrivals serialize on the counter (4x fewer than
// the 592-block shape) and 147 spinners poll the release line.
__device__ __forceinline__ void gbar(){
  __threadfence();
  __syncthreads();
  if(threadIdx.x==0){
    unsigned old = ld_acq(&g_gen);
    unsigned prev;
    asm volatile("atom.add.release.gpu.global.u32 %0,[%1],%2;":"=r"(prev):"l"(&g_count),"r"(1u):"memory");
    if(prev==NB-1u){
      asm volatile("st.relaxed.gpu.global.u32 [%0],%1;"::"l"(&g_count),"r"(0u):"memory");
      asm volatile("st.release.gpu.global.u32 [%0],%1;"::"l"(&g_gen),"r"(old+1u):"memory");
    } else {
      unsigned v;
      do { v = ld_acq(&g_gen); } while(v==old);
    }
  }
  __syncthreads();
}

__global__ void __launch_bounds__(NT,1) k_mega(
    const float* __restrict__ x, const float* __restrict__ mask, const int* __restrict__ ei,
    const float* __restrict__ gat_W, const float* __restrict__ gat_as,
    const float* __restrict__ gat_ad, const float* __restrict__ gat_b,
    const float* __restrict__ miw, const float* __restrict__ mib,
    const float* __restrict__ mow, const float* __restrict__ mob,
    const float* __restrict__ wq, const float* __restrict__ bq,
    const float* __restrict__ wk, const float* __restrict__ bk,
    const float* __restrict__ wv, const float* __restrict__ bv,
    const float* __restrict__ ws, const float* __restrict__ bs,
    const float* __restrict__ W1, const float* __restrict__ b1,
    const float* __restrict__ W2, const float* __restrict__ b2,
    const float* __restrict__ W3, const float* __restrict__ b3,
    const float* __restrict__ cw, const float* __restrict__ cb,
    float* __restrict__ out, int out_size)
{
  __shared__ float4 s_kv[2048];    // 32KB: 4 MHA m-tiles
  __shared__ float  s_red[544];

  const int t    = threadIdx.x;
  const int bid  = blockIdx.x;
  const int gtid = bid*NT + t;
  const int lane = t & 31;
  // 16-lane node groups: 64 groups/block x 148 = 9472 >= NN, one round.
  const int grp  = t >> 4;          // 0..63
  const int l16  = t & 15;
  const int node = grp*NB + bid;    // unique in [0, 9472)
  // Member mask names only this group's lanes (a warp can host one active and
  // one inactive group; full-warp mask would deadlock — R12 lesson).
  const unsigned m16 = 0xFFFFu << (lane & 16);

  // ---------- P01: GAT layer-0 node transform + CSR scatter (fused) ----------
  if(gtid < NN){
    int i=gtid;
    float h0=x[3*i], h1=x[3*i+1], h2=x[3*i+2];
    float p0 = h0*gat_W[0]+h1*gat_W[3]+h2*gat_W[6];
    float p1 = h0*gat_W[1]+h1*gat_W[4]+h2*gat_W[7];
    float p2 = h0*gat_W[2]+h1*gat_W[5]+h2*gat_W[8];
    float s  = (p0*gat_as[0]+p1*gat_as[1]+p2*gat_as[2])*L2E;
    float d  = (p0*gat_ad[0]+p1*gat_ad[1]+p2*gat_ad[2])*L2E;
    g_xp[0][i]=make_float4(p0,p1,p2,s);
    g_dvv[0][i]=d;
  }
  for(int e=gtid; e<EE; e+=NTH){
    int s = ei[e], d = ei[EE+e];
    int pos = atomicAdd(&g_deg[d],1);     // g_deg starts zero (invariant)
    if(pos < DMAX) g_csr[d*DMAX+pos]=s;
  }
  gbar();

  // ---------- P2..P11: 10 GAT layers (16 lanes/node, pipelined gathers) ----------
  // deg / csr indices are layer-invariant: hoist them once.
  int deg=0, cnt=1;
  int sidx[4]={0,0,0,0};
  if(node < NN){
    deg = min(g_deg[node], DMAX);
    cnt = deg+1;
    #pragma unroll
    for(int r=0;r<4;r++){
      int j = l16 + r*16;
      sidx[r] = (j<deg) ? g_csr[node*DMAX+j] : node;
    }
  }
  for(int l=0;l<10;l++){
    int bi = l&1;
    if(node < NN){
      int i = node;
      float d_i = __ldcg(&g_dvv[bi][i]);
      const float4* xp = g_xp[bi];
      float4 xs[4];
      #pragma unroll
      for(int r=0;r<4;r++){
        int j = l16 + r*16;
        if(j<cnt) xs[r] = __ldcg(&xp[sidx[r]]);
      }
      float z=0.f,a0=0.f,a1=0.f,a2=0.f;
      #pragma unroll
      for(int r=0;r<4;r++){
        int j = l16 + r*16;
        if(j<cnt){
          float e = xs[r].w + d_i;            // log2-scaled logit
          e = e>0.f ? e : 0.2f*e;
          float w = ex2f(e);
          z+=w; a0=fmaf(w,xs[r].x,a0); a1=fmaf(w,xs[r].y,a1); a2=fmaf(w,xs[r].z,a2);
        }
      }
      // Fallback for deg>63 (P ~ 1e-6 per node)
      for(int j=l16+64; j<cnt; j+=16){
        int s = (j<deg) ? g_csr[i*DMAX+j] : i;
        float4 xv = __ldcg(&xp[s]);
        float e = xv.w + d_i;
        e = e>0.f ? e : 0.2f*e;
        float w = ex2f(e);
        z+=w; a0=fmaf(w,xv.x,a0); a1=fmaf(w,xv.y,a1); a2=fmaf(w,xv.z,a2);
      }
      #pragma unroll
      for(int o=8;o;o>>=1){
        z +=__shfl_xor_sync(m16,z ,o,16);
        a0+=__shfl_xor_sync(m16,a0,o,16);
        a1+=__shfl_xor_sync(m16,a1,o,16);
        a2+=__shfl_xor_sync(m16,a2,o,16);
      }
      if(l16==0){
        float inv = 1.f/(z+1e-16f);
        float h0=a0*inv+gat_b[l*3+0];
        float h1=a1*inv+gat_b[l*3+1];
        float h2=a2*inv+gat_b[l*3+2];
        if(l<9){
          h0=fmaxf(h0,0.f); h1=fmaxf(h1,0.f); h2=fmaxf(h2,0.f);
          const float* W  = gat_W +(l+1)*9;
          const float* as_= gat_as+(l+1)*3;
          const float* ad = gat_ad+(l+1)*3;
          float p0=h0*W[0]+h1*W[3]+h2*W[6];
          float p1=h0*W[1]+h1*W[4]+h2*W[7];
          float p2=h0*W[2]+h1*W[5]+h2*W[8];
          float s =(p0*as_[0]+p1*as_[1]+p2*as_[2])*L2E;
          float d =(p0*ad[0]+p1*ad[1]+p2*ad[2])*L2E;
          g_xp[bi^1][i]=make_float4(p0,p1,p2,s);
          g_dvv[bi^1][i]=d;
        } else {
          float q[9];
          #pragma unroll
          for(int j=0;j<9;j++) q[j]=mib[j]+h0*miw[j*3+0]+h1*miw[j*3+1]+h2*miw[j*3+2];
          g_q[i]      =make_float4(q[0]*L2E,q[1]*L2E,q[2]*L2E,0.f);
          g_kv[2*i]   =make_float4(q[3],q[4],q[5],0.f);
          g_kv[2*i+1] =make_float4(q[6],q[7],q[8],0.f);
        }
      }
    }
    gbar();
  }

  // ---------- P12: brute MHA — 576 units (24 n-tiles x 24 m-tiles), 4/block ----------
  if(bid < 144){
    // Stage the 4 units' m-tiles: 4 x 512 float4 = 32KB
    for(int e=t; e<2048; e+=NT){
      int u = e>>9, off = e&511;
      int mtile = (bid*4+u)%24;
      s_kv[e] = g_kv[mtile*512 + off];
    }
    __syncthreads();
    int u  = t>>8;                 // 0..3: which unit
    int nl = t&255;
    int unit = bid*4 + u;
    int n = (unit/24)*256 + nl;
    const float4* kv = s_kv + u*512;
    float4 q = g_q[n];
    float z0=0,z1=0,z2=0,o0=0,o1=0,o2=0;
    #pragma unroll 8
    for(int m=0;m<256;m++){
      float4 k=kv[2*m], v=kv[2*m+1];
      float e0=ex2f(q.x*k.x);
      float e1=ex2f(q.y*k.y);
      float e2=ex2f(q.z*k.z);
      z0+=e0; z1+=e1; z2+=e2;
      o0=fmaf(e0,v.x,o0); o1=fmaf(e1,v.y,o1); o2=fmaf(e2,v.z,o2);
    }
    float* a=g_acc+n*8;                    // zeros on entry (invariant)
    atomicAdd(a+0,z0); atomicAdd(a+1,z1); atomicAdd(a+2,z2);
    atomicAdd(a+3,o0); atomicAdd(a+4,o1); atomicAdd(a+5,o2);
  }
  gbar();

  // ---------- P13: MHA finalize + TC projections; re-zero g_acc ----------
  if(gtid < NN){
    int i=gtid;
    float* a=g_acc+i*8;
    float o0=a[3]/a[0], o1=a[4]/a[1], o2=a[5]/a[2];
    #pragma unroll
    for(int k=0;k<6;k++) a[k]=0.f;         // restore invariant for next launch
    float h0=mob[0]+o0*mow[0]+o1*mow[1]+o2*mow[2];
    float h1=mob[1]+o0*mow[3]+o1*mow[4]+o2*mow[5];
    float h2=mob[2]+o0*mow[6]+o1*mow[7]+o2*mow[8];
    const float QS=0.57735026918962576f*L2E;
    float q0=(bq[0]+h0*wq[0]+h1*wq[3]+h2*wq[6])*QS;
    float q1=(bq[1]+h0*wq[1]+h1*wq[4]+h2*wq[7])*QS;
    float q2=(bq[2]+h0*wq[2]+h1*wq[5]+h2*wq[8])*QS;
    float k0= bk[0]+h0*wk[0]+h1*wk[3]+h2*wk[6];
    float k1= bk[1]+h0*wk[1]+h1*wk[4]+h2*wk[7];
    float k2= bk[2]+h0*wk[2]+h1*wk[5]+h2*wk[8];
    float v0= bv[0]+h0*wv[0]+h1*wv[3]+h2*wv[6];
    float v1= bv[1]+h0*wv[1]+h1*wv[4]+h2*wv[7];
    float v2= bv[2]+h0*wv[2]+h1*wv[5]+h2*wv[8];
    float s0= bs[0]+h0*ws[0]+h1*ws[3]+h2*ws[6];
    float s1= bs[1]+h0*ws[1]+h1*ws[4]+h2*ws[7];
    float s2= bs[2]+h0*ws[2]+h1*ws[5]+h2*ws[8];
    g_tcq[i]     =make_float4(q0,q1,q2,0.f);
    g_tckv[2*i]  =make_float4(k0,k1,k2,0.f);
    g_tckv[2*i+1]=make_float4(v0,v1,v2,0.f);
    g_skip[i]    =make_float4(s0,s1,s2,0.f);
  }
  gbar();

  // ---------- P14: TransformerConv (16 lanes/node, pipelined, reuses sidx) ----------
  if(node < NN){
    int i = node;
    float4 q = g_tcq[i];
    float z=0.f,a0=0.f,a1=0.f,a2=0.f;
    #pragma unroll
    for(int r=0;r<4;r++){
      int j = l16 + r*16;
      if(j<cnt){
        float4 k=g_tckv[2*sidx[r]];
        float4 v=g_tckv[2*sidx[r]+1];
        float lg=q.x*k.x+q.y*k.y+q.z*k.z;
        float w=ex2f(lg);
        z+=w; a0=fmaf(w,v.x,a0); a1=fmaf(w,v.y,a1); a2=fmaf(w,v.z,a2);
      }
    }
    for(int j=l16+64; j<cnt; j+=16){
      int s = (j<deg) ? g_csr[i*DMAX+j] : i;
      float4 k=g_tckv[2*s];
      float4 v=g_tckv[2*s+1];
      float lg=q.x*k.x+q.y*k.y+q.z*k.z;
      float w=ex2f(lg);
      z+=w; a0=fmaf(w,v.x,a0); a1=fmaf(w,v.y,a1); a2=fmaf(w,v.z,a2);
    }
    #pragma unroll
    for(int o=8;o;o>>=1){
      z +=__shfl_xor_sync(m16,z ,o,16);
      a0+=__shfl_xor_sync(m16,a0,o,16);
      a1+=__shfl_xor_sync(m16,a1,o,16);
      a2+=__shfl_xor_sync(m16,a2,o,16);
    }
    if(l16==0){
      float inv=1.f/(z+1e-16f);
      float4 sk=g_skip[i];
      g_flat[3*i+0]=a0*inv+sk.x;
      g_flat[3*i+1]=a1*inv+sk.y;
      g_flat[3*i+2]=a2*inv+sk.z;
      g_deg[i]=0;                          // restore invariant for next launch
    }
  }
  gbar();

  // ---------- P15: MLP layer 1 partial sums (18 blocks) ----------
  if(gtid < 3*NN){
    float xv = g_flat[gtid];
    const float4* w4 = reinterpret_cast<const float4*>(W1 + (size_t)gtid*16);
    float4 wa=w4[0], wb=w4[1], wc=w4[2], wd=w4[3];
    float p[16];
    p[0]=xv*wa.x; p[1]=xv*wa.y; p[2]=xv*wa.z; p[3]=xv*wa.w;
    p[4]=xv*wb.x; p[5]=xv*wb.y; p[6]=xv*wb.z; p[7]=xv*wb.w;
    p[8]=xv*wc.x; p[9]=xv*wc.y; p[10]=xv*wc.z; p[11]=xv*wc.w;
    p[12]=xv*wd.x; p[13]=xv*wd.y; p[14]=xv*wd.z; p[15]=xv*wd.w;
    #pragma unroll
    for(int j=0;j<16;j++){
      #pragma unroll
      for(int o=16;o;o>>=1) p[j]+=__shfl_xor_sync(0xffffffffu,p[j],o);
    }
    if(lane==0){
      int w = t>>5;                      // 0..31
      #pragma unroll
      for(int j=0;j<16;j++) s_red[j*32+w]=p[j];   // 512 floats
    }
    __syncthreads();
    if(t<16){
      float s=0.f;
      #pragma unroll
      for(int w=0;w<32;w++) s+=s_red[t*32+w];
      atomicAdd(&g_h1[t],s);               // g_h1 zero on entry (invariant)
    }
  }
  gbar();

  // ---------- P16: a2 + MLP layer 3 + mask + mean + critic (6 blocks) ----------
  if(gtid < NN){
    if(t<32){
      float s=b2[t];
      #pragma unroll
      for(int k=0;k<16;k++){
        float a1=fmaxf(g_h1[k]+b1[k],0.f);
        s=fmaf(a1,W2[k*32+t],s);
      }
      s_red[512+t]=fmaxf(s,0.f);           // a2 recomputed per block
    }
    __syncthreads();
    float r = b3[gtid];
    #pragma unroll
    for(int k=0;k<32;k++) r=fmaf(s_red[512+k],W3[k*NN+gtid],r);
    out[gtid]=r*mask[gtid];
    #pragma unroll
    for(int off=16;off;off>>=1) r+=__shfl_xor_sync(0xffffffffu,r,off);
    if(lane==0) s_red[t>>5]=r;
    __syncthreads();
    if(t==0){
      float s=0.f;
      #pragma unroll
      for(int w=0;w<32;w++) s+=s_red[w];
      atomicAdd(&g_sum,s);
      __threadfence();
      unsigned p=atomicAdd(&g_flag,1u);
      if(p==5u){                           // last of 6 participating blocks
        float tot=atomicAdd(&g_sum,0.f);
        if(out_size>NN) out[NN]=cw[0]*(tot*(1.f/(float)NN))+cb[0];
        // restore invariants for next launch
        #pragma unroll
        for(int k=0;k<16;k++) g_h1[k]=0.f;
        g_sum=0.f;
        asm volatile("st.release.gpu.global.u32 [%0],%1;"::"l"(&g_flag),"r"(0u):"memory");
      }
    }
  }
}

extern "C" void kernel_launch(void* const* d_in, const int* in_sizes, int n_in,
                              void* d_out, int out_size){
  const float* x    =(const float*)d_in[0];
  const float* mask =(const float*)d_in[1];
  const int*   ei   =(const int*)  d_in[2];
  const float* gat_W=(const float*)d_in[3];
  const float* gat_as=(const float*)d_in[4];
  const float* gat_ad=(const float*)d_in[5];
  const float* gat_b=(const float*)d_in[6];
  const float* miw  =(const float*)d_in[7];
  const float* mib  =(const float*)d_in[8];
  const float* mow  =(const float*)d_in[9];
  const float* mob  =(const float*)d_in[10];
  const float* wq=(const float*)d_in[11]; const float* bq=(const float*)d_in[12];
  const float* wk=(const float*)d_in[13]; const float* bk=(const float*)d_in[14];
  const float* wv=(const float*)d_in[15]; const float* bv=(const float*)d_in[16];
  const float* ws=(const float*)d_in[17]; const float* bs=(const float*)d_in[18];
  const float* W1=(const float*)d_in[19]; const float* b1=(const float*)d_in[20];
  const float* W2=(const float*)d_in[21]; const float* b2=(const float*)d_in[22];
  const float* W3=(const float*)d_in[23]; const float* b3=(const float*)d_in[24];
  const float* cw=(const float*)d_in[25]; const float* cb=(const float*)d_in[26];
  float* out=(float*)d_out;

  k_mega<<<NB,NT>>>(x,mask,ei,gat_W,gat_as,gat_ad,gat_b,miw,mib,mow,mob,
                    wq,bq,wk,bk,wv,bv,ws,bs,W1,b1,W2,b2,W3,b3,cw,cb,out,out_size);
}

// round 16
// speedup vs baseline: 1.0297x; 1.0297x over previous
#include <cuda_runtime.h>

#define NN 6144
#define EE 196608
#define NB 592
#define NT 256
#define NTH (NB*NT)       // 151552
#define DMAX 96
#define L2E 1.4426950408889634f

__device__ unsigned g_gen;        // zero at load; monotonic across launches
__device__ unsigned g_count;      // self-resetting

// All state below is zero at module load and restored to zero by the end of
// every launch (zero-on-last-use), so replays see identical initial state.
static __device__ int    g_deg[NN];
static __device__ int    g_csr[NN*DMAX];
static __device__ float4 g_xp[2][NN];     // xyz = xp, w = asrc*L2E
static __device__ float  g_dvv[2][NN];    // adst*L2E
static __device__ float4 g_q[NN];         // mha q * L2E
static __device__ float4 g_kv[2*NN];      // [2i]=k, [2i+1]=v
static __device__ float  g_acc[NN*8];     // z0..z2,o0..o2 (L2 atomics only); re-zeroed at finalize
static __device__ unsigned g_tile[24];    // per-n-tile completion counters; reset by finalizer
static __device__ float4 g_tcq[NN];       // q2 * (1/sqrt3)*L2E
static __device__ float4 g_tckv[2*NN];    // [2i]=k2, [2i+1]=v2
static __device__ float4 g_skip[NN];
static __device__ float  g_flat[3*NN];
static __device__ float  g_h1[16];        // atomic accum; reset by last block
static __device__ float  g_sum;           // reset by last block
static __device__ unsigned g_flag;        // reset by last block

__device__ __forceinline__ float ex2f(float x){ float y; asm("ex2.approx.ftz.f32 %0,%1;":"=f"(y):"f"(x)); return y; }
__device__ __forceinline__ unsigned ld_acq(unsigned* p){
  unsigned v; asm volatile("ld.acquire.gpu.global.u32 %0,[%1];":"=r"(v):"l"(p):"memory"); return v;
}

// Flat grid barrier — 592 co-resident blocks (4/SM x 148 SMs via
// launch_bounds(256,4)); pure spin. Measured-best config; unchanged.
__device__ __forceinline__ void gbar(){
  __threadfence();
  __syncthreads();
  if(threadIdx.x==0){
    unsigned old = ld_acq(&g_gen);
    unsigned prev;
    asm volatile("atom.add.release.gpu.global.u32 %0,[%1],%2;":"=r"(prev):"l"(&g_count),"r"(1u):"memory");
    if(prev==NB-1u){
      asm volatile("st.relaxed.gpu.global.u32 [%0],%1;"::"l"(&g_count),"r"(0u):"memory");
      asm volatile("st.release.gpu.global.u32 [%0],%1;"::"l"(&g_gen),"r"(old+1u):"memory");
    } else {
      unsigned v;
      do { v = ld_acq(&g_gen); } while(v==old);
    }
  }
  __syncthreads();
}

__global__ void __launch_bounds__(NT,4) k_mega(
    const float* __restrict__ x, const float* __restrict__ mask, const int* __restrict__ ei,
    const float* __restrict__ gat_W, const float* __restrict__ gat_as,
    const float* __restrict__ gat_ad, const float* __restrict__ gat_b,
    const float* __restrict__ miw, const float* __restrict__ mib,
    const float* __restrict__ mow, const float* __restrict__ mob,
    const float* __restrict__ wq, const float* __restrict__ bq,
    const float* __restrict__ wk, const float* __restrict__ bk,
    const float* __restrict__ wv, const float* __restrict__ bv,
    const float* __restrict__ ws, const float* __restrict__ bs,
    const float* __restrict__ W1, const float* __restrict__ b1,
    const float* __restrict__ W2, const float* __restrict__ b2,
    const float* __restrict__ W3, const float* __restrict__ b3,
    const float* __restrict__ cw, const float* __restrict__ cb,
    float* __restrict__ out, int out_size)
{
  __shared__ float4 s_kv[512];     // 8KB MHA tile
  __shared__ float  s_red[160];
  __shared__ unsigned s_lastf;

  const int t    = threadIdx.x;
  const int bid  = blockIdx.x;
  const int gtid = bid*NT + t;
  const int lane = t & 31;
  // 16-lane node groups: every node in ONE round (9472 groups >= 6144 nodes).
  const int grp  = t >> 4;          // 0..15 within block
  const int l16  = t & 15;
  const int node = grp*NB + bid;    // unique in [0, 9472)
  // Member mask names only this group's lanes (a warp can host one active and
  // one inactive group; full-warp mask would deadlock — R12 lesson).
  const unsigned m16 = 0xFFFFu << (lane & 16);

  // ---------- P01: GAT layer-0 node transform + CSR scatter (fused) ----------
  if(gtid < NN){
    int i=gtid;
    float h0=x[3*i], h1=x[3*i+1], h2=x[3*i+2];
    float p0 = h0*gat_W[0]+h1*gat_W[3]+h2*gat_W[6];
    float p1 = h0*gat_W[1]+h1*gat_W[4]+h2*gat_W[7];
    float p2 = h0*gat_W[2]+h1*gat_W[5]+h2*gat_W[8];
    float s  = (p0*gat_as[0]+p1*gat_as[1]+p2*gat_as[2])*L2E;
    float d  = (p0*gat_ad[0]+p1*gat_ad[1]+p2*gat_ad[2])*L2E;
    g_xp[0][i]=make_float4(p0,p1,p2,s);
    g_dvv[0][i]=d;
  }
  for(int e=gtid; e<EE; e+=NTH){
    int s = ei[e], d = ei[EE+e];
    int pos = atomicAdd(&g_deg[d],1);     // g_deg starts zero (invariant)
    if(pos < DMAX) g_csr[d*DMAX+pos]=s;
  }
  gbar();

  // ---------- P2..P11: 10 GAT layers (16 lanes/node, pipelined gathers) ----------
  for(int l=0;l<10;l++){
    int bi = l&1;
    if(node < NN){
      int i = node;
      // Preload next-layer weights BEFORE the gathers so these (first-touch
      // L2) loads pipeline under the xp gathers instead of sitting serially
      // in the lane-0 epilogue. Broadcast across the 16 lanes (same lines).
      int ln = (l<9)? l+1 : 9;             // harmless dummy row for l==9
      const float* Wp = gat_W + ln*9;
      const float* ap = gat_as+ ln*3;
      const float* dp = gat_ad+ ln*3;
      float bb0=gat_b[l*3+0], bb1=gat_b[l*3+1], bb2=gat_b[l*3+2];
      float w0=Wp[0],w1=Wp[1],w2=Wp[2],w3=Wp[3],w4=Wp[4],w5=Wp[5],w6=Wp[6],w7=Wp[7],w8=Wp[8];
      float ua0=ap[0],ua1=ap[1],ua2=ap[2];
      float ud0=dp[0],ud1=dp[1],ud2=dp[2];
      int deg = min(g_deg[i], DMAX);
      int cnt = deg+1;
      float d_i = __ldcg(&g_dvv[bi][i]);
      const float4* xp = g_xp[bi];
      int   sidx[4];
      float4 xs[4];
      #pragma unroll
      for(int r=0;r<4;r++){
        int j = l16 + r*16;
        sidx[r] = (j<deg) ? g_csr[i*DMAX+j] : i;
      }
      #pragma unroll
      for(int r=0;r<4;r++){
        int j = l16 + r*16;
        if(j<cnt) xs[r] = __ldcg(&xp[sidx[r]]);
      }
      float z=0.f,a0=0.f,a1=0.f,a2=0.f;
      #pragma unroll
      for(int r=0;r<4;r++){
        int j = l16 + r*16;
        if(j<cnt){
          float e = xs[r].w + d_i;            // log2-scaled logit
          e = e>0.f ? e : 0.2f*e;
          float w = ex2f(e);
          z+=w; a0=fmaf(w,xs[r].x,a0); a1=fmaf(w,xs[r].y,a1); a2=fmaf(w,xs[r].z,a2);
        }
      }
      // Fallback for deg>63 (P ~ 1e-6 per node; essentially never runs)
      for(int j=l16+64; j<cnt; j+=16){
        int s = (j<deg) ? g_csr[i*DMAX+j] : i;
        float4 xv = __ldcg(&xp[s]);
        float e = xv.w + d_i;
        e = e>0.f ? e : 0.2f*e;
        float w = ex2f(e);
        z+=w; a0=fmaf(w,xv.x,a0); a1=fmaf(w,xv.y,a1); a2=fmaf(w,xv.z,a2);
      }
      #pragma unroll
      for(int o=8;o;o>>=1){
        z +=__shfl_xor_sync(m16,z ,o,16);
        a0+=__shfl_xor_sync(m16,a0,o,16);
        a1+=__shfl_xor_sync(m16,a1,o,16);
        a2+=__shfl_xor_sync(m16,a2,o,16);
      }
      if(l16==0){
        float inv = 1.f/(z+1e-16f);
        float h0=a0*inv+bb0;
        float h1=a1*inv+bb1;
        float h2=a2*inv+bb2;
        if(l<9){
          h0=fmaxf(h0,0.f); h1=fmaxf(h1,0.f); h2=fmaxf(h2,0.f);
          float p0=h0*w0+h1*w3+h2*w6;
          float p1=h0*w1+h1*w4+h2*w7;
          float p2=h0*w2+h1*w5+h2*w8;
          float s =(p0*ua0+p1*ua1+p2*ua2)*L2E;
          float d =(p0*ud0+p1*ud1+p2*ud2)*L2E;
          g_xp[bi^1][i]=make_float4(p0,p1,p2,s);
          g_dvv[bi^1][i]=d;
        } else {
          float q[9];
          #pragma unroll
          for(int j=0;j<9;j++) q[j]=mib[j]+h0*miw[j*3+0]+h1*miw[j*3+1]+h2*miw[j*3+2];
          g_q[i]      =make_float4(q[0]*L2E,q[1]*L2E,q[2]*L2E,0.f);
          g_kv[2*i]   =make_float4(q[3],q[4],q[5],0.f);
          g_kv[2*i+1] =make_float4(q[6],q[7],q[8],0.f);
        }
      }
    }
    gbar();
  }

  // ---------- P12: brute MHA + fused per-tile finalize ----------
  // 576 units = 24 n-tiles x 24 m-tiles. The LAST block to finish an n-tile
  // (per-tile release counter) finalizes that tile's 256 nodes inline,
  // overlapping with other tiles' MHA work. One global barrier covers both.
  if(bid < 576){
    int ntile = bid/24, mtile = bid%24;
    int mb = mtile*512;                    // 256 kv pairs = 512 float4
    s_kv[t]     = g_kv[mb+t];
    s_kv[t+256] = g_kv[mb+256+t];
    __syncthreads();
    int n = ntile*256 + t;
    float4 q = g_q[n];
    float z0=0,z1=0,z2=0,o0=0,o1=0,o2=0;
    #pragma unroll 8
    for(int m=0;m<256;m++){
      float4 k=s_kv[2*m], v=s_kv[2*m+1];
      float e0=ex2f(q.x*k.x);
      float e1=ex2f(q.y*k.y);
      float e2=ex2f(q.z*k.z);
      z0+=e0; z1+=e1; z2+=e2;
      o0=fmaf(e0,v.x,o0); o1=fmaf(e1,v.y,o1); o2=fmaf(e2,v.z,o2);
    }
    float* a=g_acc+n*8;                    // zeros on entry (invariant)
    atomicAdd(a+0,z0); atomicAdd(a+1,z1); atomicAdd(a+2,z2);
    atomicAdd(a+3,o0); atomicAdd(a+4,o1); atomicAdd(a+5,o2);
    __threadfence();                       // release our atomics
    if(t==0){
      unsigned prev;
      asm volatile("atom.add.release.gpu.global.u32 %0,[%1],%2;":"=r"(prev):"l"(&g_tile[ntile]),"r"(1u):"memory");
      s_lastf = (prev==23u) ? 1u : 0u;
    }
    __syncthreads();
    if(s_lastf){
      // All 24 m-blocks' atomics are in L2 (g_acc only ever touched by L2
      // atomics; reads via __ldcg hit the same coherence point).
      if(t==0) g_tile[ntile]=0u;           // reset invariant for next launch
      int i = ntile*256 + t;
      float* a2p=g_acc+i*8;
      float z0f=__ldcg(a2p+0), z1f=__ldcg(a2p+1), z2f=__ldcg(a2p+2);
      float o0f=__ldcg(a2p+3), o1f=__ldcg(a2p+4), o2f=__ldcg(a2p+5);
      float oo0=o0f/z0f, oo1=o1f/z1f, oo2=o2f/z2f;
      #pragma unroll
      for(int k=0;k<6;k++) a2p[k]=0.f;     // restore invariant for next launch
      float h0=mob[0]+oo0*mow[0]+oo1*mow[1]+oo2*mow[2];
      float h1=mob[1]+oo0*mow[3]+oo1*mow[4]+oo2*mow[5];
      float h2=mob[2]+oo0*mow[6]+oo1*mow[7]+oo2*mow[8];
      const float QS=0.57735026918962576f*L2E;
      float q0=(bq[0]+h0*wq[0]+h1*wq[3]+h2*wq[6])*QS;
      float q1=(bq[1]+h0*wq[1]+h1*wq[4]+h2*wq[7])*QS;
      float q2=(bq[2]+h0*wq[2]+h1*wq[5]+h2*wq[8])*QS;
      float k0= bk[0]+h0*wk[0]+h1*wk[3]+h2*wk[6];
      float k1= bk[1]+h0*wk[1]+h1*wk[4]+h2*wk[7];
      float k2= bk[2]+h0*wk[2]+h1*wk[5]+h2*wk[8];
      float v0= bv[0]+h0*wv[0]+h1*wv[3]+h2*wv[6];
      float v1= bv[1]+h0*wv[1]+h1*wv[4]+h2*wv[7];
      float v2= bv[2]+h0*wv[2]+h1*wv[5]+h2*wv[8];
      float s0= bs[0]+h0*ws[0]+h1*ws[3]+h2*ws[6];
      float s1= bs[1]+h0*ws[1]+h1*ws[4]+h2*ws[7];
      float s2= bs[2]+h0*ws[2]+h1*ws[5]+h2*ws[8];
      g_tcq[i]     =make_float4(q0,q1,q2,0.f);
      g_tckv[2*i]  =make_float4(k0,k1,k2,0.f);
      g_tckv[2*i+1]=make_float4(v0,v1,v2,0.f);
      g_skip[i]    =make_float4(s0,s1,s2,0.f);
    }
  }
  gbar();

  // ---------- P14: TransformerConv (16 lanes/node, pipelined gathers) ----------
  if(node < NN){
    int i = node;
    int deg = min(g_deg[i], DMAX);
    int cnt = deg+1;
    float4 q = g_tcq[i];
    int sidx[4];
    #pragma unroll
    for(int r=0;r<4;r++){
      int j = l16 + r*16;
      sidx[r] = (j<deg) ? g_csr[i*DMAX+j] : i;
    }
    float z=0.f,a0=0.f,a1=0.f,a2=0.f;
    #pragma unroll
    for(int r=0;r<4;r++){
      int j = l16 + r*16;
      if(j<cnt){
        float4 k=g_tckv[2*sidx[r]];
        float4 v=g_tckv[2*sidx[r]+1];
        float lg=q.x*k.x+q.y*k.y+q.z*k.z;
        float w=ex2f(lg);
        z+=w; a0=fmaf(w,v.x,a0); a1=fmaf(w,v.y,a1); a2=fmaf(w,v.z,a2);
      }
    }
    for(int j=l16+64; j<cnt; j+=16){
      int s = (j<deg) ? g_csr[i*DMAX+j] : i;
      float4 k=g_tckv[2*s];
      float4 v=g_tckv[2*s+1];
      float lg=q.x*k.x+q.y*k.y+q.z*k.z;
      float w=ex2f(lg);
      z+=w; a0=fmaf(w,v.x,a0); a1=fmaf(w,v.y,a1); a2=fmaf(w,v.z,a2);
    }
    #pragma unroll
    for(int o=8;o;o>>=1){
      z +=__shfl_xor_sync(m16,z ,o,16);
      a0+=__shfl_xor_sync(m16,a0,o,16);
      a1+=__shfl_xor_sync(m16,a1,o,16);
      a2+=__shfl_xor_sync(m16,a2,o,16);
    }
    if(l16==0){
      float inv=1.f/(z+1e-16f);
      float4 sk=g_skip[i];
      g_flat[3*i+0]=a0*inv+sk.x;
      g_flat[3*i+1]=a1*inv+sk.y;
      g_flat[3*i+2]=a2*inv+sk.z;
      g_deg[i]=0;                          // restore invariant for next launch
    }
  }
  gbar();

  // ---------- P15: MLP layer 1 partial sums (72 blocks) ----------
  if(gtid < 3*NN){
    float xv = g_flat[gtid];
    const float4* w4 = reinterpret_cast<const float4*>(W1 + (size_t)gtid*16);
    float4 wa=w4[0], wb=w4[1], wc=w4[2], wd=w4[3];
    float p[16];
    p[0]=xv*wa.x; p[1]=xv*wa.y; p[2]=xv*wa.z; p[3]=xv*wa.w;
    p[4]=xv*wb.x; p[5]=xv*wb.y; p[6]=xv*wb.z; p[7]=xv*wb.w;
    p[8]=xv*wc.x; p[9]=xv*wc.y; p[10]=xv*wc.z; p[11]=xv*wc.w;
    p[12]=xv*wd.x; p[13]=xv*wd.y; p[14]=xv*wd.z; p[15]=xv*wd.w;
    #pragma unroll
    for(int j=0;j<16;j++){
      #pragma unroll
      for(int o=16;o;o>>=1) p[j]+=__shfl_xor_sync(0xffffffffu,p[j],o);
    }
    if(lane==0){
      int w8=t>>5;
      #pragma unroll
      for(int j=0;j<16;j++) s_red[j*8+w8]=p[j];
    }
    __syncthreads();
    if(t<16){
      float s=0.f;
      #pragma unroll
      for(int w8=0;w8<8;w8++) s+=s_red[t*8+w8];
      atomicAdd(&g_h1[t],s);               // g_h1 zero on entry (invariant)
    }
  }
  gbar();

  // ---------- P16: a2 + MLP layer 3 + mask + mean + critic (24 blocks) ----------
  if(gtid < NN){
    if(t<32){
      float s=b2[t];
      #pragma unroll
      for(int k=0;k<16;k++){
        float a1=fmaxf(g_h1[k]+b1[k],0.f);
        s=fmaf(a1,W2[k*32+t],s);
      }
      s_red[128+t]=fmaxf(s,0.f);           // a2 recomputed per block
    }
    __syncthreads();
    float r = b3[gtid];
    #pragma unroll
    for(int k=0;k<32;k++) r=fmaf(s_red[128+k],W3[k*NN+gtid],r);
    out[gtid]=r*mask[gtid];
    #pragma unroll
    for(int off=16;off;off>>=1) r+=__shfl_xor_sync(0xffffffffu,r,off);
    if(lane==0) s_red[t>>5]=r;
    __syncthreads();
    if(t==0){
      float s=0.f;
      #pragma unroll
      for(int w8=0;w8<8;w8++) s+=s_red[w8];
      atomicAdd(&g_sum,s);
      __threadfence();
      unsigned p=atomicAdd(&g_flag,1u);
      if(p==23u){                          // last of 24 participating blocks
        float tot=atomicAdd(&g_sum,0.f);
        if(out_size>NN) out[NN]=cw[0]*(tot*(1.f/(float)NN))+cb[0];
        // restore invariants for next launch
        #pragma unroll
        for(int k=0;k<16;k++) g_h1[k]=0.f;
        g_sum=0.f;
        asm volatile("st.release.gpu.global.u32 [%0],%1;"::"l"(&g_flag),"r"(0u):"memory");
      }
    }
  }
}

extern "C" void kernel_launch(void* const* d_in, const int* in_sizes, int n_in,
                              void* d_out, int out_size){
  const float* x    =(const float*)d_in[0];
  const float* mask =(const float*)d_in[1];
  const int*   ei   =(const int*)  d_in[2];
  const float* gat_W=(const float*)d_in[3];
  const float* gat_as=(const float*)d_in[4];
  const float* gat_ad=(const float*)d_in[5];
  const float* gat_b=(const float*)d_in[6];
  const float* miw  =(const float*)d_in[7];
  const float* mib  =(const float*)d_in[8];
  const float* mow  =(const float*)d_in[9];
  const float* mob  =(const float*)d_in[10];
  const float* wq=(const float*)d_in[11]; const float* bq=(const float*)d_in[12];
  const float* wk=(const float*)d_in[13]; const float* bk=(const float*)d_in[14];
  const float* wv=(const float*)d_in[15]; const float* bv=(const float*)d_in[16];
  const float* ws=(const float*)d_in[17]; const float* bs=(const float*)d_in[18];
  const float* W1=(const float*)d_in[19]; const float* b1=(const float*)d_in[20];
  const float* W2=(const float*)d_in[21]; const float* b2=(const float*)d_in[22];
  const float* W3=(const float*)d_in[23]; const float* b3=(const float*)d_in[24];
  const float* cw=(const float*)d_in[25]; const float* cb=(const float*)d_in[26];
  float* out=(float*)d_out;

  k_mega<<<NB,NT>>>(x,mask,ei,gat_W,gat_as,gat_ad,gat_b,miw,mib,mow,mob,
                    wq,bq,wk,bk,wv,bv,ws,bs,W1,b1,W2,b2,W3,b3,cw,cb,out,out_size);
}